// round 17
// baseline (speedup 1.0000x reference)
#include <cuda_runtime.h>
#include <cuda_bf16.h>
#include <math.h>
#include <stdint.h>

#define BB 2
#define SS 2048
#define DM 768
#define NH 12
#define DH 64
#define MROWS (BB*SS)
#define NZ (BB*NH)

static const long long OUT_ELEMS  = (long long)BB * SS * DM;            // 3,145,728
static const long long ATTN_ELEMS = (long long)BB * NH * SS * SS;       // 100,663,296

// ---------------------------------------------------------------------------
// Scratch (allocation-free rule: static __device__ arrays)
// ---------------------------------------------------------------------------
__device__ __align__(16) unsigned short g_xqh[MROWS*DM], g_xql[MROWS*DM];
__device__ __align__(16) unsigned short g_xkh[MROWS*DM], g_xkl[MROWS*DM];
__device__ __align__(16) unsigned short g_xvh[MROWS*DM], g_xvl[MROWS*DM];
__device__ __align__(16) unsigned short g_wqh[DM*DM], g_wql[DM*DM];
__device__ __align__(16) unsigned short g_wkh[DM*DM], g_wkl[DM*DM];
__device__ __align__(16) unsigned short g_wvh[DM*DM], g_wvl[DM*DM];
__device__ __align__(16) unsigned short g_woh[DM*DM], g_wol[DM*DM];
__device__ __align__(16) unsigned short g_Qh[MROWS*DM], g_Ql[MROWS*DM];
__device__ __align__(16) unsigned short g_Kh[MROWS*DM], g_Kl[MROWS*DM];
__device__ __align__(16) unsigned short g_VTh[NZ*DH*SS], g_VTl[NZ*DH*SS]; // [(b,h,d)][s]
__device__ __align__(16) unsigned short g_ch[MROWS*DM], g_cl[MROWS*DM];
__device__ __align__(16) float g_stats[(long long)NZ*SS*64*2];   // per (z,row,coltile32): (max, expsum)
__device__ __align__(16) float g_rstats[(long long)NZ*SS*2];     // per (z,row): (M, 1/sum)
__device__ __align__(16) float g_attn_f[(long long)NZ*SS*SS];    // fallback if attn not in d_out

// ---------------------------------------------------------------------------
// helpers
// ---------------------------------------------------------------------------
__device__ __forceinline__ void cp16(uint32_t saddr, const void* gptr)
{
    asm volatile("cp.async.cg.shared.global [%0], [%1], 16;" :: "r"(saddr), "l"(gptr));
}

__device__ __forceinline__ void mma16816(float d[4], const uint32_t a[4], const uint32_t b[2])
{
    asm volatile(
        "mma.sync.aligned.m16n8k16.row.col.f32.bf16.bf16.f32 "
        "{%0,%1,%2,%3}, {%4,%5,%6,%7}, {%8,%9}, {%0,%1,%2,%3};"
        : "+f"(d[0]), "+f"(d[1]), "+f"(d[2]), "+f"(d[3])
        : "r"(a[0]), "r"(a[1]), "r"(a[2]), "r"(a[3]), "r"(b[0]), "r"(b[1]));
}

__device__ __forceinline__ unsigned short us(__nv_bfloat16 h) { return __bfloat16_as_ushort(h); }

__device__ __forceinline__ void store_split2(unsigned short* ph, unsigned short* pl,
                                             float x, float y)
{
    __nv_bfloat16 hx = __float2bfloat16_rn(x), hy = __float2bfloat16_rn(y);
    __nv_bfloat16 lx = __float2bfloat16_rn(x - __bfloat162float(hx));
    __nv_bfloat16 ly = __float2bfloat16_rn(y - __bfloat162float(hy));
    ushort2 hv; hv.x = us(hx); hv.y = us(hy);
    ushort2 lv; lv.x = us(lx); lv.y = us(ly);
    *(ushort2*)ph = hv; *(ushort2*)pl = lv;
}

__device__ __forceinline__ void store_split1(unsigned short* ph, unsigned short* pl, float x)
{
    __nv_bfloat16 hx = __float2bfloat16_rn(x);
    __nv_bfloat16 lx = __float2bfloat16_rn(x - __bfloat162float(hx));
    *ph = us(hx); *pl = us(lx);
}

__device__ __forceinline__ void pack4(float4 v, uint2& h, uint2& l)
{
    __nv_bfloat16 h0 = __float2bfloat16_rn(v.x), h1 = __float2bfloat16_rn(v.y);
    __nv_bfloat16 h2 = __float2bfloat16_rn(v.z), h3 = __float2bfloat16_rn(v.w);
    __nv_bfloat16 l0 = __float2bfloat16_rn(v.x - __bfloat162float(h0));
    __nv_bfloat16 l1 = __float2bfloat16_rn(v.y - __bfloat162float(h1));
    __nv_bfloat16 l2 = __float2bfloat16_rn(v.z - __bfloat162float(h2));
    __nv_bfloat16 l3 = __float2bfloat16_rn(v.w - __bfloat162float(h3));
    h.x = (uint32_t)us(h0) | ((uint32_t)us(h1) << 16);
    h.y = (uint32_t)us(h2) | ((uint32_t)us(h3) << 16);
    l.x = (uint32_t)us(l0) | ((uint32_t)us(l1) << 16);
    l.y = (uint32_t)us(l2) | ((uint32_t)us(l3) << 16);
}

// ---------------------------------------------------------------------------
// batched split: grid.y selects (src, dst) tuple; all tuples same n4.
// ---------------------------------------------------------------------------
__global__ void split_multi(const float4* __restrict__ s0, const float4* __restrict__ s1,
                            const float4* __restrict__ s2, const float4* __restrict__ s3,
                            uint2* h0, uint2* h1, uint2* h2, uint2* h3,
                            uint2* l0, uint2* l1, uint2* l2, uint2* l3,
                            int n4)
{
    const float4* ss[4] = { s0, s1, s2, s3 };
    uint2* hh[4] = { h0, h1, h2, h3 };
    uint2* ll[4] = { l0, l1, l2, l3 };
    int w = blockIdx.y;
    int i = blockIdx.x * blockDim.x + threadIdx.x;
    if (i >= n4) return;
    uint2 hp, lp;
    pack4(ss[w][i], hp, lp);
    hh[w][i] = hp; ll[w][i] = lp;
}

// ===========================================================================
// Merged QKV projection GEMM. blockIdx.z in {0,1,2} selects (X, W, b, dst).
// z<2: C split hi/lo row-major. z==2: V split hi/lo transposed (V^T layout).
// ===========================================================================
__global__ __launch_bounds__(256, 2) void gemm_qkv(
    const unsigned short* __restrict__ xqh_, const unsigned short* __restrict__ xql_,
    const unsigned short* __restrict__ xkh_, const unsigned short* __restrict__ xkl_,
    const unsigned short* __restrict__ xvh_, const unsigned short* __restrict__ xvl_,
    const unsigned short* __restrict__ wqh_, const unsigned short* __restrict__ wql_,
    const unsigned short* __restrict__ wkh_, const unsigned short* __restrict__ wkl_,
    const unsigned short* __restrict__ wvh_, const unsigned short* __restrict__ wvl_,
    const float* __restrict__ b_q, const float* __restrict__ b_k, const float* __restrict__ b_v,
    unsigned short* __restrict__ Qh_, unsigned short* __restrict__ Ql_,
    unsigned short* __restrict__ Kh_, unsigned short* __restrict__ Kl_,
    unsigned short* __restrict__ VTh_, unsigned short* __restrict__ VTl_)
{
    constexpr int BM = 128, BN = 128;
    constexpr int WM = 2, WN = 4;
    constexpr int WTM = BM / WM, WTN = BN / WN;
    constexpr int TM = WTM / 16, TN = WTN / 8;
    constexpr int ROWU = 20;
    constexpr int ASZ = BM * ROWU, BSZ = BN * ROWU;

    extern __shared__ uint32_t sm[];
    uint32_t* sAh_ = sm;
    uint32_t* sAl_ = sm + 2 * ASZ;
    uint32_t* sBh_ = sm + 4 * ASZ;
    uint32_t* sBl_ = sBh_ + 2 * BSZ;

    const int tid = threadIdx.x, lane = tid & 31, warp = tid >> 5;
    const int g = lane >> 2, t = lane & 3;
    const int wm = warp % WM, wn = warp / WM;
    const int wrow0 = wm * WTM, wcol0 = wn * WTN;

    const int z = blockIdx.z;
    const unsigned short *Ahg, *Alg, *Bhg, *Blg;
    const float* bias;
    if (z == 0)      { Ahg = xqh_; Alg = xql_; Bhg = wqh_; Blg = wql_; bias = b_q; }
    else if (z == 1) { Ahg = xkh_; Alg = xkl_; Bhg = wkh_; Blg = wkl_; bias = b_k; }
    else             { Ahg = xvh_; Alg = xvl_; Bhg = wvh_; Blg = wvl_; bias = b_v; }

    const int row0 = blockIdx.y * BM;
    const int col0 = blockIdx.x * BN;

    const uint32_t aAh = (uint32_t)__cvta_generic_to_shared(sAh_);
    const uint32_t aAl = (uint32_t)__cvta_generic_to_shared(sAl_);
    const uint32_t aBh = (uint32_t)__cvta_generic_to_shared(sBh_);
    const uint32_t aBl = (uint32_t)__cvta_generic_to_shared(sBl_);

    float acc[TM][TN][4] = {};
    constexpr int KT = DM / 32;  // 24

    auto load_slab = [&](int kt, int buf) {
        const int k0 = kt * 32;
        {
            int r = tid >> 1, c = tid & 1;
            long long go = (long long)(row0 + r) * DM + k0 + c * 16;
            uint32_t so = (uint32_t)(buf * ASZ + r * ROWU + c * 8) * 4u;
            cp16(aAh + so,      Ahg + go);
            cp16(aAh + so + 16, Ahg + go + 8);
            cp16(aAl + so,      Alg + go);
            cp16(aAl + so + 16, Alg + go + 8);
        }
        {
            int r = tid >> 1, c = tid & 1;
            long long go = (long long)(col0 + r) * DM + k0 + c * 16;
            uint32_t so = (uint32_t)(buf * BSZ + r * ROWU + c * 8) * 4u;
            cp16(aBh + so,      Bhg + go);
            cp16(aBh + so + 16, Bhg + go + 8);
            cp16(aBl + so,      Blg + go);
            cp16(aBl + so + 16, Blg + go + 8);
        }
        asm volatile("cp.async.commit_group;" ::: "memory");
    };

    auto compute = [&](int buf) {
        const uint32_t* Abh = sAh_ + buf * ASZ;
        const uint32_t* Abl = sAl_ + buf * ASZ;
        const uint32_t* Bbh = sBh_ + buf * BSZ;
        const uint32_t* Bbl = sBl_ + buf * BSZ;
#pragma unroll
        for (int ks = 0; ks < 2; ++ks) {
            const int c = t + ks * 8;
            uint32_t bh[TN][2], bl[TN][2];
#pragma unroll
            for (int nt = 0; nt < TN; ++nt) {
                int n = wcol0 + nt * 8 + g;
                bh[nt][0] = Bbh[n * ROWU + c]; bh[nt][1] = Bbh[n * ROWU + c + 4];
                bl[nt][0] = Bbl[n * ROWU + c]; bl[nt][1] = Bbl[n * ROWU + c + 4];
            }
#pragma unroll
            for (int mt = 0; mt < TM; ++mt) {
                int m = wrow0 + mt * 16 + g;
                uint32_t ah[4] = { Abh[m*ROWU+c], Abh[(m+8)*ROWU+c],
                                   Abh[m*ROWU+c+4], Abh[(m+8)*ROWU+c+4] };
                uint32_t al[4] = { Abl[m*ROWU+c], Abl[(m+8)*ROWU+c],
                                   Abl[m*ROWU+c+4], Abl[(m+8)*ROWU+c+4] };
#pragma unroll
                for (int nt = 0; nt < TN; ++nt) {
                    mma16816(acc[mt][nt], ah, bh[nt]);
                    mma16816(acc[mt][nt], ah, bl[nt]);
                    mma16816(acc[mt][nt], al, bh[nt]);
                }
            }
        }
    };

    load_slab(0, 0);
    for (int kt = 0; kt < KT; ++kt) {
        if (kt + 1 < KT) {
            load_slab(kt + 1, (kt + 1) & 1);
            asm volatile("cp.async.wait_group 1;" ::: "memory");
        } else {
            asm volatile("cp.async.wait_group 0;" ::: "memory");
        }
        __syncthreads();
        compute(kt & 1);
        __syncthreads();
    }

#pragma unroll
    for (int mt = 0; mt < TM; ++mt) {
#pragma unroll
        for (int nt = 0; nt < TN; ++nt) {
            int m = row0 + wrow0 + mt * 16 + g;
            int n = col0 + wcol0 + nt * 8 + 2 * t;
            float b0 = bias[n], b1 = bias[n + 1];
            float v00 = acc[mt][nt][0] + b0;
            float v01 = acc[mt][nt][1] + b1;
            float v10 = acc[mt][nt][2] + b0;
            float v11 = acc[mt][nt][3] + b1;
            if (z < 2) {
                unsigned short* Ch = (z == 0) ? Qh_ : Kh_;
                unsigned short* Cl = (z == 0) ? Ql_ : Kl_;
                store_split2(Ch + (long long)m * DM + n, Cl + (long long)m * DM + n, v00, v01);
                store_split2(Ch + (long long)(m + 8) * DM + n, Cl + (long long)(m + 8) * DM + n, v10, v11);
            } else {
                auto vt = [](int mm, int nn) -> long long {
                    int b = mm >> 11, s = mm & 2047, h = nn >> 6, d = nn & 63;
                    return (((long long)(b * NH + h) * DH + d) << 11) + s;
                };
                store_split1(VTh_ + vt(m, n),         VTl_ + vt(m, n),         v00);
                store_split1(VTh_ + vt(m, n + 1),     VTl_ + vt(m, n + 1),     v01);
                store_split1(VTh_ + vt(m + 8, n),     VTl_ + vt(m + 8, n),     v10);
                store_split1(VTh_ + vt(m + 8, n + 1), VTl_ + vt(m + 8, n + 1), v11);
            }
        }
    }
}

// ===========================================================================
// Specialized scores GEMM (K=64, single-shot smem, one __syncthreads).
// C[m,n] = (Q[m,:].K[n,:])/8 -> fp32 attn + per-(row, 32-col tile) stats.
// BM=BN=128, 256 threads. ROWU=36 (32 data u32 + 4 pad), conflict-free.
// ===========================================================================
__global__ __launch_bounds__(256, 2) void gemm_scores(
    const unsigned short* __restrict__ Qh_, const unsigned short* __restrict__ Ql_,
    const unsigned short* __restrict__ Kh_, const unsigned short* __restrict__ Kl_,
    float* __restrict__ Cf, float* __restrict__ stats)
{
    constexpr int BM = 128, BN = 128;
    constexpr int WM = 2, WN = 4;
    constexpr int WTM = BM / WM, WTN = BN / WN;   // 64, 32
    constexpr int TM = WTM / 16, TN = WTN / 8;    // 4, 4
    constexpr int ROWU = 36;                      // 32 data u32 + 4 pad
    constexpr int TSZ = BM * ROWU;                // per array

    extern __shared__ uint32_t sm[];
    uint32_t* sAh_ = sm;
    uint32_t* sAl_ = sm + TSZ;
    uint32_t* sBh_ = sm + 2 * TSZ;
    uint32_t* sBl_ = sm + 3 * TSZ;

    const int tid = threadIdx.x, lane = tid & 31, warp = tid >> 5;
    const int g = lane >> 2, t = lane & 3;
    const int wm = warp % WM, wn = warp / WM;
    const int wrow0 = wm * WTM, wcol0 = wn * WTN;

    const int z = blockIdx.z;
    const int zb = z / NH, zh = z % NH;
    const long long qoff = (long long)zb * SS * DM + (long long)zh * DH;
    const long long coff = (long long)z * SS * SS;

    const int row0 = blockIdx.y * BM;
    const int col0 = blockIdx.x * BN;

    const uint32_t aAh = (uint32_t)__cvta_generic_to_shared(sAh_);
    const uint32_t aAl = (uint32_t)__cvta_generic_to_shared(sAl_);
    const uint32_t aBh = (uint32_t)__cvta_generic_to_shared(sBh_);
    const uint32_t aBl = (uint32_t)__cvta_generic_to_shared(sBl_);

    // load entire K=64 extent: per array, row r has 8 chunks of 16B; thread
    // (r = tid>>1, c = tid&1) copies chunks c*4..c*4+3 (64B half-row).
    {
        int r = tid >> 1, c = tid & 1;
        long long goA = qoff + (long long)(row0 + r) * DM + c * 32;
        long long goB = qoff + (long long)(col0 + r) * DM + c * 32;
        uint32_t so = (uint32_t)(r * ROWU + c * 16) * 4u;
#pragma unroll
        for (int j = 0; j < 4; ++j) {
            cp16(aAh + so + j * 16, Qh_ + goA + j * 8);
            cp16(aAl + so + j * 16, Ql_ + goA + j * 8);
            cp16(aBh + so + j * 16, Kh_ + goB + j * 8);
            cp16(aBl + so + j * 16, Kl_ + goB + j * 8);
        }
    }
    asm volatile("cp.async.commit_group;" ::: "memory");
    asm volatile("cp.async.wait_group 0;" ::: "memory");
    __syncthreads();

    float acc[TM][TN][4] = {};
#pragma unroll
    for (int ks = 0; ks < 4; ++ks) {
        const int c = t + ks * 8;
        uint32_t bh[TN][2], bl[TN][2];
#pragma unroll
        for (int nt = 0; nt < TN; ++nt) {
            int n = wcol0 + nt * 8 + g;
            bh[nt][0] = sBh_[n * ROWU + c]; bh[nt][1] = sBh_[n * ROWU + c + 4];
            bl[nt][0] = sBl_[n * ROWU + c]; bl[nt][1] = sBl_[n * ROWU + c + 4];
        }
#pragma unroll
        for (int mt = 0; mt < TM; ++mt) {
            int m = wrow0 + mt * 16 + g;
            uint32_t ah[4] = { sAh_[m*ROWU+c], sAh_[(m+8)*ROWU+c],
                               sAh_[m*ROWU+c+4], sAh_[(m+8)*ROWU+c+4] };
            uint32_t al[4] = { sAl_[m*ROWU+c], sAl_[(m+8)*ROWU+c],
                               sAl_[m*ROWU+c+4], sAl_[(m+8)*ROWU+c+4] };
#pragma unroll
            for (int nt = 0; nt < TN; ++nt) {
                mma16816(acc[mt][nt], ah, bh[nt]);
                mma16816(acc[mt][nt], ah, bl[nt]);
                mma16816(acc[mt][nt], al, bh[nt]);
            }
        }
    }

    // epilogue: scaled fp32 store + per-(row, 32-col warp tile) stats
#pragma unroll
    for (int mt = 0; mt < TM; ++mt) {
        float va[2 * TN], vb[2 * TN];
#pragma unroll
        for (int nt = 0; nt < TN; ++nt) {
            int m = row0 + wrow0 + mt * 16 + g;
            int n = col0 + wcol0 + nt * 8 + 2 * t;
            va[2*nt]   = 0.125f * acc[mt][nt][0];
            va[2*nt+1] = 0.125f * acc[mt][nt][1];
            vb[2*nt]   = 0.125f * acc[mt][nt][2];
            vb[2*nt+1] = 0.125f * acc[mt][nt][3];
            float2 u0; u0.x = va[2*nt]; u0.y = va[2*nt+1];
            float2 u1; u1.x = vb[2*nt]; u1.y = vb[2*nt+1];
            *(float2*)&Cf[coff + (long long)m * SS + n] = u0;
            *(float2*)&Cf[coff + (long long)(m + 8) * SS + n] = u1;
        }
        float mx0 = va[0], mx1 = vb[0];
#pragma unroll
        for (int j = 1; j < 2 * TN; ++j) { mx0 = fmaxf(mx0, va[j]); mx1 = fmaxf(mx1, vb[j]); }
        mx0 = fmaxf(mx0, __shfl_xor_sync(0xffffffffu, mx0, 1));
        mx0 = fmaxf(mx0, __shfl_xor_sync(0xffffffffu, mx0, 2));
        mx1 = fmaxf(mx1, __shfl_xor_sync(0xffffffffu, mx1, 1));
        mx1 = fmaxf(mx1, __shfl_xor_sync(0xffffffffu, mx1, 2));
        float s0 = 0.f, s1 = 0.f;
#pragma unroll
        for (int j = 0; j < 2 * TN; ++j) { s0 += __expf(va[j] - mx0); s1 += __expf(vb[j] - mx1); }
        s0 += __shfl_xor_sync(0xffffffffu, s0, 1);
        s0 += __shfl_xor_sync(0xffffffffu, s0, 2);
        s1 += __shfl_xor_sync(0xffffffffu, s1, 1);
        s1 += __shfl_xor_sync(0xffffffffu, s1, 2);
        if (t == 0) {
            int m  = row0 + wrow0 + mt * 16 + g;
            int ct = (col0 + wcol0) >> 5;
            long long si0 = ((((long long)z << 11) + m)     * 64 + ct) * 2;
            long long si1 = ((((long long)z << 11) + m + 8) * 64 + ct) * 2;
            float2 p0; p0.x = mx0; p0.y = s0;
            float2 p1; p1.x = mx1; p1.y = s1;
            *(float2*)&stats[si0] = p0;
            *(float2*)&stats[si1] = p1;
        }
    }
}

// ===========================================================================
// Generic pre-split GEMM, EPI0 (fp32 C + bias). Used for out projection.
// ===========================================================================
__global__ __launch_bounds__(256, 2) void gemm_sp0(
    const unsigned short* __restrict__ Ahg, const unsigned short* __restrict__ Alg,
    const unsigned short* __restrict__ Bhg, const unsigned short* __restrict__ Blg,
    const float* __restrict__ bias, float* __restrict__ Cf,
    int K, int lda, int ldb, int ldc)
{
    constexpr int BM = 128, BN = 128;
    constexpr int WM = 2, WN = 4;
    constexpr int WTM = BM / WM, WTN = BN / WN;
    constexpr int TM = WTM / 16, TN = WTN / 8;
    constexpr int ROWU = 20;
    constexpr int ASZ = BM * ROWU, BSZ = BN * ROWU;

    extern __shared__ uint32_t sm[];
    uint32_t* sAh_ = sm;
    uint32_t* sAl_ = sm + 2 * ASZ;
    uint32_t* sBh_ = sm + 4 * ASZ;
    uint32_t* sBl_ = sBh_ + 2 * BSZ;

    const int tid = threadIdx.x, lane = tid & 31, warp = tid >> 5;
    const int g = lane >> 2, t = lane & 3;
    const int wm = warp % WM, wn = warp / WM;
    const int wrow0 = wm * WTM, wcol0 = wn * WTN;

    const int row0 = blockIdx.y * BM;
    const int col0 = blockIdx.x * BN;

    const uint32_t aAh = (uint32_t)__cvta_generic_to_shared(sAh_);
    const uint32_t aAl = (uint32_t)__cvta_generic_to_shared(sAl_);
    const uint32_t aBh = (uint32_t)__cvta_generic_to_shared(sBh_);
    const uint32_t aBl = (uint32_t)__cvta_generic_to_shared(sBl_);

    float acc[TM][TN][4] = {};
    const int KT = K / 32;

    auto load_slab = [&](int kt, int buf) {
        const int k0 = kt * 32;
        {
            int r = tid >> 1, c = tid & 1;
            long long go = (long long)(row0 + r) * lda + k0 + c * 16;
            uint32_t so = (uint32_t)(buf * ASZ + r * ROWU + c * 8) * 4u;
            cp16(aAh + so,      Ahg + go);
            cp16(aAh + so + 16, Ahg + go + 8);
            cp16(aAl + so,      Alg + go);
            cp16(aAl + so + 16, Alg + go + 8);
        }
        {
            int r = tid >> 1, c = tid & 1;
            long long go = (long long)(col0 + r) * ldb + k0 + c * 16;
            uint32_t so = (uint32_t)(buf * BSZ + r * ROWU + c * 8) * 4u;
            cp16(aBh + so,      Bhg + go);
            cp16(aBh + so + 16, Bhg + go + 8);
            cp16(aBl + so,      Blg + go);
            cp16(aBl + so + 16, Blg + go + 8);
        }
        asm volatile("cp.async.commit_group;" ::: "memory");
    };

    auto compute = [&](int buf) {
        const uint32_t* Abh = sAh_ + buf * ASZ;
        const uint32_t* Abl = sAl_ + buf * ASZ;
        const uint32_t* Bbh = sBh_ + buf * BSZ;
        const uint32_t* Bbl = sBl_ + buf * BSZ;
#pragma unroll
        for (int ks = 0; ks < 2; ++ks) {
            const int c = t + ks * 8;
            uint32_t bh[TN][2], bl[TN][2];
#pragma unroll
            for (int nt = 0; nt < TN; ++nt) {
                int n = wcol0 + nt * 8 + g;
                bh[nt][0] = Bbh[n * ROWU + c]; bh[nt][1] = Bbh[n * ROWU + c + 4];
                bl[nt][0] = Bbl[n * ROWU + c]; bl[nt][1] = Bbl[n * ROWU + c + 4];
            }
#pragma unroll
            for (int mt = 0; mt < TM; ++mt) {
                int m = wrow0 + mt * 16 + g;
                uint32_t ah[4] = { Abh[m*ROWU+c], Abh[(m+8)*ROWU+c],
                                   Abh[m*ROWU+c+4], Abh[(m+8)*ROWU+c+4] };
                uint32_t al[4] = { Abl[m*ROWU+c], Abl[(m+8)*ROWU+c],
                                   Abl[m*ROWU+c+4], Abl[(m+8)*ROWU+c+4] };
#pragma unroll
                for (int nt = 0; nt < TN; ++nt) {
                    mma16816(acc[mt][nt], ah, bh[nt]);
                    mma16816(acc[mt][nt], ah, bl[nt]);
                    mma16816(acc[mt][nt], al, bh[nt]);
                }
            }
        }
    };

    load_slab(0, 0);
    for (int kt = 0; kt < KT; ++kt) {
        if (kt + 1 < KT) {
            load_slab(kt + 1, (kt + 1) & 1);
            asm volatile("cp.async.wait_group 1;" ::: "memory");
        } else {
            asm volatile("cp.async.wait_group 0;" ::: "memory");
        }
        __syncthreads();
        compute(kt & 1);
        __syncthreads();
    }

#pragma unroll
    for (int mt = 0; mt < TM; ++mt) {
#pragma unroll
        for (int nt = 0; nt < TN; ++nt) {
            int m = row0 + wrow0 + mt * 16 + g;
            int n = col0 + wcol0 + nt * 8 + 2 * t;
            float b0 = bias[n], b1 = bias[n + 1];
            float2 u0; u0.x = acc[mt][nt][0] + b0; u0.y = acc[mt][nt][1] + b1;
            float2 u1; u1.x = acc[mt][nt][2] + b0; u1.y = acc[mt][nt][3] + b1;
            *(float2*)&Cf[(long long)m * ldc + n] = u0;
            *(float2*)&Cf[(long long)(m + 8) * ldc + n] = u1;
        }
    }
}

// ---------------------------------------------------------------------------
// Row stats reduce: per row, merge 64 (max, expsum) tiles -> (M, 1/sum).
// ---------------------------------------------------------------------------
__global__ __launch_bounds__(256) void rowstats_reduce(const float* __restrict__ stats,
                                                       float* __restrict__ rstats)
{
    const int warp = threadIdx.x >> 5, lane = threadIdx.x & 31;
    const long long row = (long long)blockIdx.x * 8 + warp;
    const float2* sp = (const float2*)(stats + row * 64 * 2);
    float2 a = sp[lane], b = sp[lane + 32];
    float M = fmaxf(a.x, b.x);
    float S = a.y * __expf(a.x - M) + b.y * __expf(b.x - M);
#pragma unroll
    for (int d = 16; d > 0; d >>= 1) {
        float Mo = __shfl_xor_sync(0xffffffffu, M, d);
        float So = __shfl_xor_sync(0xffffffffu, S, d);
        float Mn = fmaxf(M, Mo);
        S = S * __expf(M - Mn) + So * __expf(Mo - Mn);
        M = Mn;
    }
    if (lane == 0) {
        float2 r; r.x = M; r.y = 1.f / S;
        *(float2*)&rstats[row * 2] = r;
    }
}

// ---------------------------------------------------------------------------
// AV GEMM with fused softmax. BM=64 (768 CTAs -> better wave balance).
// A = RAW scores fp32; exp(s-M)*inv applied in-reg; optionally writes
// normalized probs to attn. B = pre-split V^T. BN=64, BK=32, 256 thr.
// grid: (SS/64, NZ)
// ---------------------------------------------------------------------------
__global__ __launch_bounds__(256, 2) void gemm_av(
    const float* __restrict__ attn_in, float* __restrict__ attn_out,
    const float* __restrict__ rstats,
    const unsigned short* __restrict__ Bhg, const unsigned short* __restrict__ Blg,
    unsigned short* __restrict__ Ch, unsigned short* __restrict__ Cl,
    int write_attn)
{
    constexpr int BM = 64, BN = 64;
    constexpr int WM = 4, WN = 2;
    constexpr int WTM = BM / WM, WTN = BN / WN;   // 16, 32
    constexpr int TM = WTM / 16, TN = WTN / 8;    // 1, 4
    constexpr int ROWU = 20;
    constexpr int ASZ = BM * ROWU, BSZ = BN * ROWU;   // 1280 each

    extern __shared__ uint32_t sm[];
    uint32_t* sAh_ = sm;                          // [2][ASZ]
    uint32_t* sAl_ = sm + 2 * ASZ;
    uint32_t* sBh_ = sm + 4 * ASZ;
    uint32_t* sBl_ = sBh_ + 2 * BSZ;

    const int tid = threadIdx.x, lane = tid & 31, warp = tid >> 5;
    const int g = lane >> 2, t = lane & 3;
    const int wm = warp % WM, wn = warp / WM;
    const int wrow0 = wm * WTM, wcol0 = wn * WTN;

    const int z = blockIdx.y;
    const int zb = z / NH, zh = z % NH;
    const long long aoff = (long long)z * SS * SS;
    const long long boff = (long long)z * DH * SS;
    const long long coff = (long long)zb * SS * DM + (long long)zh * DH;

    const int row0 = blockIdx.x * BM;

    const uint32_t aBh = (uint32_t)__cvta_generic_to_shared(sBh_);
    const uint32_t aBl = (uint32_t)__cvta_generic_to_shared(sBl_);

    float acc[TM][TN][4] = {};
    constexpr int KT = SS / 32;                   // 64
    float4 ra[2];

    // per-thread row softmax stats (rows r = tid/8 + i*32)
    float2 st[2];
#pragma unroll
    for (int i = 0; i < 2; ++i)
        st[i] = ((const float2*)rstats)[((long long)z << 11) + row0 + tid / 8 + i * 32];

    auto loadAreg = [&](int kt) {
        const int k0 = kt * 32;
#pragma unroll
        for (int i = 0; i < 2; ++i) {
            int r = tid / 8 + i * 32;
            int c = (tid & 7) * 4;
            ra[i] = *(const float4*)&attn_in[aoff + (long long)(row0 + r) * SS + k0 + c];
        }
    };
    auto storeA = [&](int buf, int kt) {
        const int k0 = kt * 32;
#pragma unroll
        for (int i = 0; i < 2; ++i) {
            int r  = tid / 8 + i * 32;
            int cu = (tid & 7) * 2;
            float4 v = ra[i];
            v.x = __expf(v.x - st[i].x) * st[i].y;
            v.y = __expf(v.y - st[i].x) * st[i].y;
            v.z = __expf(v.z - st[i].x) * st[i].y;
            v.w = __expf(v.w - st[i].x) * st[i].y;
            if (write_attn) {
                int c = (tid & 7) * 4;
                *(float4*)&attn_out[aoff + (long long)(row0 + r) * SS + k0 + c] = v;
            }
            uint2 hp, lp;
            pack4(v, hp, lp);
            *(uint2*)&sAh_[buf * ASZ + r * ROWU + cu] = hp;
            *(uint2*)&sAl_[buf * ASZ + r * ROWU + cu] = lp;
        }
    };
    auto cpB = [&](int kt, int buf) {
        const int k0 = kt * 32;
        int r = (tid & 127) >> 1, c = tid & 1;
        long long go = (long long)r * SS + k0 + c * 16 + boff;
        uint32_t so = (uint32_t)(buf * BSZ + r * ROWU + c * 8) * 4u;
        if (tid < 128) {
            cp16(aBh + so,      Bhg + go);
            cp16(aBh + so + 16, Bhg + go + 8);
        } else {
            cp16(aBl + so,      Blg + go);
            cp16(aBl + so + 16, Blg + go + 8);
        }
        asm volatile("cp.async.commit_group;" ::: "memory");
    };
    auto compute = [&](int buf) {
        const uint32_t* Abh = sAh_ + buf * ASZ;
        const uint32_t* Abl = sAl_ + buf * ASZ;
        const uint32_t* Bbh = sBh_ + buf * BSZ;
        const uint32_t* Bbl = sBl_ + buf * BSZ;
#pragma unroll
        for (int ks = 0; ks < 2; ++ks) {
            const int c = t + ks * 8;
            uint32_t bh[TN][2], bl[TN][2];
#pragma unroll
            for (int nt = 0; nt < TN; ++nt) {
                int n = wcol0 + nt * 8 + g;
                bh[nt][0] = Bbh[n * ROWU + c]; bh[nt][1] = Bbh[n * ROWU + c + 4];
                bl[nt][0] = Bbl[n * ROWU + c]; bl[nt][1] = Bbl[n * ROWU + c + 4];
            }
            {
                int m = wrow0 + g;
                uint32_t ah[4] = { Abh[m*ROWU+c], Abh[(m+8)*ROWU+c],
                                   Abh[m*ROWU+c+4], Abh[(m+8)*ROWU+c+4] };
                uint32_t al[4] = { Abl[m*ROWU+c], Abl[(m+8)*ROWU+c],
                                   Abl[m*ROWU+c+4], Abl[(m+8)*ROWU+c+4] };
#pragma unroll
                for (int nt = 0; nt < TN; ++nt) {
                    mma16816(acc[0][nt], ah, bh[nt]);
                    mma16816(acc[0][nt], ah, bl[nt]);
                    mma16816(acc[0][nt], al, bh[nt]);
                }
            }
        }
    };

    // prologue
    loadAreg(0);
    cpB(0, 0);
    storeA(0, 0);
    asm volatile("cp.async.wait_group 0;" ::: "memory");
    __syncthreads();

    for (int kt = 0; kt < KT; ++kt) {
        if (kt + 1 < KT) {
            loadAreg(kt + 1);
            cpB(kt + 1, (kt + 1) & 1);
        }
        compute(kt & 1);
        __syncthreads();
        if (kt + 1 < KT) {
            storeA((kt + 1) & 1, kt + 1);
            asm volatile("cp.async.wait_group 0;" ::: "memory");
            __syncthreads();
        }
    }

#pragma unroll
    for (int nt = 0; nt < TN; ++nt) {
        int m = row0 + wrow0 + g;
        int n = wcol0 + nt * 8 + 2 * t;
        store_split2(Ch + coff + (long long)m * DM + n,
                     Cl + coff + (long long)m * DM + n,
                     acc[0][nt][0], acc[0][nt][1]);
        store_split2(Ch + coff + (long long)(m + 8) * DM + n,
                     Cl + coff + (long long)(m + 8) * DM + n,
                     acc[0][nt][2], acc[0][nt][3]);
    }
}

// ---------------------------------------------------------------------------
extern "C" void kernel_launch(void* const* d_in, const int* in_sizes, int n_in,
                              void* d_out, int out_size)
{
    const float* query = (const float*)d_in[0];
    const float* key_  = (const float*)d_in[1];
    const float* value = (const float*)d_in[2];
    const float* W_q   = (const float*)d_in[3];
    const float* b_q   = (const float*)d_in[4];
    const float* W_k   = (const float*)d_in[5];
    const float* b_k   = (const float*)d_in[6];
    const float* W_v   = (const float*)d_in[7];
    const float* b_v   = (const float*)d_in[8];
    const float* W_o   = (const float*)d_in[9];
    const float* b_o   = (const float*)d_in[10];

    float* out = (float*)d_out;

    static bool inited = false;
    static unsigned short *xqh,*xql,*xkh,*xkl,*xvh,*xvl;
    static unsigned short *wqh,*wql,*wkh,*wkl,*wvh,*wvl,*woh,*wol;
    static unsigned short *Qh,*Ql,*Kh,*Kl,*VTh,*VTl,*ch,*cl;
    static float *attn_f, *stats, *rstats;
    if (!inited) {
        inited = true;
        cudaGetSymbolAddress((void**)&xqh, g_xqh); cudaGetSymbolAddress((void**)&xql, g_xql);
        cudaGetSymbolAddress((void**)&xkh, g_xkh); cudaGetSymbolAddress((void**)&xkl, g_xkl);
        cudaGetSymbolAddress((void**)&xvh, g_xvh); cudaGetSymbolAddress((void**)&xvl, g_xvl);
        cudaGetSymbolAddress((void**)&wqh, g_wqh); cudaGetSymbolAddress((void**)&wql, g_wql);
        cudaGetSymbolAddress((void**)&wkh, g_wkh); cudaGetSymbolAddress((void**)&wkl, g_wkl);
        cudaGetSymbolAddress((void**)&wvh, g_wvh); cudaGetSymbolAddress((void**)&wvl, g_wvl);
        cudaGetSymbolAddress((void**)&woh, g_woh); cudaGetSymbolAddress((void**)&wol, g_wol);
        cudaGetSymbolAddress((void**)&Qh,  g_Qh);  cudaGetSymbolAddress((void**)&Ql,  g_Ql);
        cudaGetSymbolAddress((void**)&Kh,  g_Kh);  cudaGetSymbolAddress((void**)&Kl,  g_Kl);
        cudaGetSymbolAddress((void**)&VTh, g_VTh); cudaGetSymbolAddress((void**)&VTl, g_VTl);
        cudaGetSymbolAddress((void**)&ch,  g_ch);  cudaGetSymbolAddress((void**)&cl,  g_cl);
        cudaGetSymbolAddress((void**)&attn_f, g_attn_f);
        cudaGetSymbolAddress((void**)&stats,  g_stats);
        cudaGetSymbolAddress((void**)&rstats, g_rstats);
        cudaFuncSetAttribute(gemm_qkv,    cudaFuncAttributeMaxDynamicSharedMemorySize, 81920);
        cudaFuncSetAttribute(gemm_scores, cudaFuncAttributeMaxDynamicSharedMemorySize, 73728);
        cudaFuncSetAttribute(gemm_sp0,    cudaFuncAttributeMaxDynamicSharedMemorySize, 81920);
        cudaFuncSetAttribute(gemm_av,     cudaFuncAttributeMaxDynamicSharedMemorySize, 40960);
    }

    const int attn_in_out = ((long long)out_size >= OUT_ELEMS + ATTN_ELEMS) ? 1 : 0;
    float* attn = attn_in_out ? out + OUT_ELEMS : attn_f;

    // 0) split raw inputs (3) + weights (4) to bf16 hi/lo
    {
        int n4i = MROWS * DM / 4;
        int n4w = DM * DM / 4;
        dim3 gi((n4i + 255) / 256, 3);
        split_multi<<<gi, 256>>>((const float4*)query, (const float4*)key_,
                                 (const float4*)value, (const float4*)value,
                                 (uint2*)xqh, (uint2*)xkh, (uint2*)xvh, (uint2*)xvh,
                                 (uint2*)xql, (uint2*)xkl, (uint2*)xvl, (uint2*)xvl,
                                 n4i);
        dim3 gw((n4w + 255) / 256, 4);
        split_multi<<<gw, 256>>>((const float4*)W_q, (const float4*)W_k,
                                 (const float4*)W_v, (const float4*)W_o,
                                 (uint2*)wqh, (uint2*)wkh, (uint2*)wvh, (uint2*)woh,
                                 (uint2*)wql, (uint2*)wkl, (uint2*)wvl, (uint2*)wol,
                                 n4w);
    }

    // 1) merged QKV projections
    {
        dim3 grd(DM / 128, MROWS / 128, 3);
        gemm_qkv<<<grd, 256, 81920>>>(xqh, xql, xkh, xkl, xvh, xvl,
                                      wqh, wql, wkh, wkl, wvh, wvl,
                                      b_q, b_k, b_v,
                                      Qh, Ql, Kh, Kl, VTh, VTl);
    }

    // 2) scores = (Q.K)/8 -> attn (raw fp32) + per-tile softmax stats
    {
        dim3 grd(SS / 128, SS / 128, NZ);
        gemm_scores<<<grd, 256, 73728>>>(Qh, Ql, Kh, Kl, attn, stats);
    }

    // 3) reduce per-tile stats -> per-row (max, 1/sum)
    rowstats_reduce<<<NZ * SS / 8, 256>>>(stats, rstats);

    // 4) ctx = softmax(scores) @ V (softmax fused; writes normalized attn)
    {
        dim3 grd(SS / 64, NZ);
        gemm_av<<<grd, 256, 40960>>>(attn, attn, rstats, VTh, VTl, ch, cl, attn_in_out);
    }

    // 5) out = ctx @ W_o^T + b_o
    {
        dim3 grd(DM / 128, MROWS / 128, 1);
        gemm_sp0<<<grd, 256, 81920>>>(ch, cl, woh, wol, b_o, out, DM, DM, DM, DM);
    }
}